// round 11
// baseline (speedup 1.0000x reference)
#include <cuda_runtime.h>
#include <cstdint>

#define NOBJ 25
#define ROWF 100          // floats per canvas row (25*4)
#define SPC  128          // samples per CTA (8 m-tiles)
#define ASTR 76           // row stride in floats (conflict-free ldmatrix)

// dynamic smem layout (floats): sB[256*76] | sA0[128*76] | sA1[128*76] | sSeq[128*25 float4]
#define SB_F   (256 * ASTR)              // 19456
#define SA_F   (SPC * ASTR)              // 9728
#define OFF_A0 SB_F
#define OFF_A1 (SB_F + SA_F)
#define OFF_SEQ (SB_F + 2 * SA_F)        // 38912 floats (byte 155648, 16B aligned)
#define SMEM_TOTAL ((OFF_SEQ + SPC * NOBJ * 4) * 4)   // 206848 B

__device__ int   g_Tmax;
__device__ float g_Bmat[256 * 72];   // folded weight matrix, gate-permuted rows, tf32-rounded

// ---------------- helpers ----------------
__device__ __forceinline__ uint32_t f2tf32(float x) {
    uint32_t r; asm("cvt.rna.tf32.f32 %0, %1;" : "=r"(r) : "f"(x)); return r;
}

__device__ __forceinline__ void mma8(float& d0, float& d1, float& d2, float& d3,
                                     uint32_t a0, uint32_t a1, uint32_t a2, uint32_t a3,
                                     uint32_t b0, uint32_t b1) {
    asm volatile("mma.sync.aligned.m16n8k8.row.col.f32.tf32.tf32.f32 "
                 "{%0,%1,%2,%3}, {%4,%5,%6,%7}, {%8,%9}, {%0,%1,%2,%3};"
                 : "+f"(d0), "+f"(d1), "+f"(d2), "+f"(d3)
                 : "r"(a0), "r"(a1), "r"(a2), "r"(a3), "r"(b0), "r"(b1));
}

__device__ __forceinline__ void ldm_x4(uint32_t& r0, uint32_t& r1, uint32_t& r2, uint32_t& r3,
                                       uint32_t addr) {
    asm volatile("ldmatrix.sync.aligned.m8n8.x4.shared.b16 {%0,%1,%2,%3}, [%4];"
                 : "=r"(r0), "=r"(r1), "=r"(r2), "=r"(r3) : "r"(addr));
}

__device__ __forceinline__ void bar_half(int bid) {
    asm volatile("bar.sync %0, 256;" :: "r"(bid) : "memory");
}

__device__ __forceinline__ float tanhapx(float x) {
    float y; asm("tanh.approx.f32 %0, %1;" : "=f"(y) : "f"(x)); return y;
}
__device__ __forceinline__ float sigm_t(float x) {
    return fmaf(tanhapx(0.5f * x), 0.5f, 0.5f);
}

// ---------------- Kernel 0: folded, gate-permuted B matrix [256][72] ----------------
// n-row mapping: tile=n>>3, pair=(n&7)>>1, which=n&1; u=((tile>>1)<<2)+pair;
// gate = even tile ? (which?f:i) : (which?o:g)   [torch i,f,g,o]
__global__ void precompute_kernel(const float* __restrict__ W_emb, const float* __restrict__ b_emb,
                                  const float* __restrict__ W_ih,  const float* __restrict__ W_hh,
                                  const float* __restrict__ b_ih,  const float* __restrict__ b_hh) {
    const int n = threadIdx.x;            // 256 threads, one B-row each
    if (n == 0) g_Tmax = 0;
    const int tile = n >> 3, pair = (n & 7) >> 1, which = n & 1;
    const int u = ((tile >> 1) << 2) + pair;
    const int gate = (tile & 1) ? (2 + which) : which;
    const int wr = gate * 64 + u;

    float* dst = g_Bmat + n * 72;
    for (int k = 0; k < 64; k++)
        dst[k] = __uint_as_float(f2tf32(W_hh[wr * 64 + k]));

    float a0 = 0.f, a1 = 0.f, a2 = 0.f, a3 = 0.f, bias = 0.f;
    for (int k = 0; k < 64; k++) {
        const float wih = W_ih[wr * 64 + k];
        a0 = fmaf(wih, W_emb[k * 4 + 0], a0);
        a1 = fmaf(wih, W_emb[k * 4 + 1], a1);
        a2 = fmaf(wih, W_emb[k * 4 + 2], a2);
        a3 = fmaf(wih, W_emb[k * 4 + 3], a3);
        bias = fmaf(wih, b_emb[k], bias);
    }
    bias += b_ih[wr] + b_hh[wr];
    dst[64] = __uint_as_float(f2tf32(a0));
    dst[65] = __uint_as_float(f2tf32(a1));
    dst[66] = __uint_as_float(f2tf32(a2));
    dst[67] = __uint_as_float(f2tf32(a3));
    dst[68] = __uint_as_float(f2tf32(bias));
    dst[69] = 0.f; dst[70] = 0.f; dst[71] = 0.f;
}

// ---------------- Kernel 1: batch-wide max valid-object count ----------------
__global__ void count_kernel(const float* __restrict__ canvas, int B) {
    __shared__ int smax;
    if (threadIdx.x == 0) smax = 0;
    __syncthreads();
    const int warp = blockIdx.x * (blockDim.x >> 5) + (threadIdx.x >> 5);
    const int lane = threadIdx.x & 31;
    if (warp < B) {
        int valid = 0;
        if (lane < NOBJ) {
            const float4 v = *reinterpret_cast<const float4*>(canvas + (size_t)warp * ROWF + lane * 4);
            valid = (((v.x + v.y) + v.z) + v.w >= 0.0f) ? 1 : 0;
        }
        const unsigned msk = __ballot_sync(0xFFFFFFFFu, valid);
        if (lane == 0 && msk) atomicMax(&smax, __popc(msk));
    }
    __syncthreads();
    if (threadIdx.x == 0 && smax > 0) atomicMax(&g_Tmax, smax);
}

// ---------------- Kernel 2: tf32 mma.sync LSTM, 128 samples/CTA, 512 threads ----------------
// Two INDEPENDENT halves (mh = w>>3 = tid>>8), each 8 warps / 64 samples, synced by
// named barrier (1+mh) only — halves free-run phase-shifted so one half's MUFU epilogue
// overlaps the other half's HMMA phase.
// Warp w: col-group wg=w&7 (gate cols [32wg,32wg+32) = units [8wg,8wg+8)).
// Thread (gid=lane>>2, tig=lane&3): units u0=8wg+tig, u1=u0+4.
__global__ void __launch_bounds__(512, 1) lstm_kernel(const float* __restrict__ canvas,
                                                      float* __restrict__ out, int B) {
    extern __shared__ float smf[];
    float* sB = smf;
    float* sAbuf[2] = { smf + OFF_A0, smf + OFF_A1 };
    float4* sSeq = reinterpret_cast<float4*>(smf + OFF_SEQ);

    const int tid  = threadIdx.x;
    const int w    = tid >> 5, lane = tid & 31;
    const int wg   = w & 7, mh = w >> 3;
    const int ltid = tid & 255;                 // tid within half (mh == tid>>8)
    const int gid  = lane >> 2, tig = lane & 3;
    const int u0   = wg * 8 + tig, u1 = u0 + 4;
    const int nw   = wg * 32;
    const int ctaBase = blockIdx.x * SPC;

    // ldmatrix lane addressing
    const int r8 = lane & 7;
    const int a_row = ((lane >> 3) & 1) * 8 + r8;    // A: row within m-tile
    const int a_col = (lane >> 4) * 4;               // A: tf32 col within k-chunk
    const int b_row = ((lane >> 4)) * 8 + r8;        // B: row within n-tile PAIR
    const int b_col = ((lane >> 3) & 1) * 4;         // B: tf32 col within k-chunk
    const uint32_t sBaddr = (uint32_t)__cvta_generic_to_shared(sB);
    const uint32_t sAaddr[2] = { (uint32_t)__cvta_generic_to_shared(sAbuf[0]),
                                 (uint32_t)__cvta_generic_to_shared(sAbuf[1]) };

    // Load B [256][72] -> sB [256][76] (tf32-rounded already)
    for (int i = tid; i < 256 * 72; i += 512) {
        const int n = i / 72, k = i - n * 72;
        sB[n * ASTR + k] = g_Bmat[i];
    }
    // Zero A buffers
    for (int i = tid; i < 2 * SA_F; i += 512) smf[OFF_A0 + i] = 0.0f;
    __syncthreads();
    if (tid < SPC) { sAbuf[0][tid * ASTR + 68] = 1.0f; sAbuf[1][tid * ASTR + 68] = 1.0f; }

    // Compaction: 16 warps x 8 samples, stable-compact, pad -1
    #pragma unroll
    for (int m = 0; m < 8; m++) {
        const int s = w * 8 + m;
        const int b = ctaBase + s;
        float4 v = make_float4(-1.f, -1.f, -1.f, -1.f);
        int valid = 0;
        if (b < B && lane < NOBJ) {
            v = *reinterpret_cast<const float4*>(canvas + (size_t)b * ROWF + lane * 4);
            valid = (((v.x + v.y) + v.z) + v.w >= 0.0f) ? 1 : 0;
        }
        const unsigned msk = __ballot_sync(0xFFFFFFFFu, valid);
        const int cnt = __popc(msk);
        if (lane < NOBJ) {
            if (valid) sSeq[s * NOBJ + __popc(msk & ((1u << lane) - 1u))] = v;
            if (lane >= cnt) sSeq[s * NOBJ + lane] = make_float4(-1.f, -1.f, -1.f, -1.f);
        }
    }

    float c_[16];
    #pragma unroll
    for (int i = 0; i < 16; i++) c_[i] = 0.f;

    const int T = g_Tmax;
    __syncthreads();

    // x_0 into buffer 0 (tf32-rounded)
    if (tid < SPC) {
        const float4 x = sSeq[tid * NOBJ + 0];
        float4 xr;
        xr.x = __uint_as_float(f2tf32(x.x));
        xr.y = __uint_as_float(f2tf32(x.y));
        xr.z = __uint_as_float(f2tf32(x.z));
        xr.w = __uint_as_float(f2tf32(x.w));
        *reinterpret_cast<float4*>(sAbuf[0] + tid * ASTR + 64) = xr;
    }
    __syncthreads();   // last CTA-wide barrier; halves decouple from here

    const int barid = 1 + mh;                  // named barrier per half
    const int mrow0 = mh * 64;                 // this half's A-row base

    for (int t = 0; t < T; t++) {
        const uint32_t aBase = sAaddr[t & 1];
        float* sAn = sAbuf[(t & 1) ^ 1];
        const bool last = (t == T - 1);

        float acc[4][4][4];
        #pragma unroll
        for (int mt = 0; mt < 4; mt++)
            #pragma unroll
            for (int nt = 0; nt < 4; nt++)
                #pragma unroll
                for (int e = 0; e < 4; e++) acc[mt][nt][e] = 0.f;

        #pragma unroll
        for (int kc = 0; kc < 9; kc++) {
            uint32_t bfr[2][4];
            #pragma unroll
            for (int p = 0; p < 2; p++) {
                const uint32_t addr = sBaddr +
                    (((nw + p * 16 + b_row) * ASTR) + kc * 8 + b_col) * 4u;
                ldm_x4(bfr[p][0], bfr[p][1], bfr[p][2], bfr[p][3], addr);
            }
            uint32_t af[4][4];
            #pragma unroll
            for (int mt = 0; mt < 4; mt++) {
                const uint32_t addr = aBase +
                    (((mrow0 + mt * 16 + a_row) * ASTR) + kc * 8 + a_col) * 4u;
                ldm_x4(af[mt][0], af[mt][1], af[mt][2], af[mt][3], addr);
            }
            #pragma unroll
            for (int mt = 0; mt < 4; mt++)
                #pragma unroll
                for (int nt = 0; nt < 4; nt++)
                    mma8(acc[mt][nt][0], acc[mt][nt][1], acc[mt][nt][2], acc[mt][nt][3],
                         af[mt][0], af[mt][1], af[mt][2], af[mt][3],
                         bfr[nt >> 1][(nt & 1) * 2], bfr[nt >> 1][(nt & 1) * 2 + 1]);
        }

        // Epilogue: 16 (sample,unit) updates; h -> NEXT buffer (tf32); final step -> gmem fp32
        #pragma unroll
        for (int mt = 0; mt < 4; mt++) {
            const int s0 = mrow0 + mt * 16 + gid;
            #pragma unroll
            for (int q = 0; q < 4; q++) {
                const int ntA = (q >> 1) * 2;
                const int e   = (q & 1) * 2;
                const float iv = acc[mt][ntA][e + 0];
                const float fv = acc[mt][ntA][e + 1];
                const float gv = acc[mt][ntA + 1][e + 0];
                const float ov = acc[mt][ntA + 1][e + 1];
                const int ci = mt * 4 + q;
                const float cn = sigm_t(fv) * c_[ci] + sigm_t(iv) * tanhapx(gv);
                c_[ci] = cn;
                const float hn = sigm_t(ov) * tanhapx(cn);
                const int s = s0 + (q & 1) * 8;
                const int u = (q >> 1) ? u1 : u0;
                sAn[s * ASTR + u] = __uint_as_float(f2tf32(hn));
                if (last) {
                    const int b = ctaBase + s;
                    if (b < B) out[(size_t)b * 64 + u] = hn;
                }
            }
        }

        // x_{t+1} into next buffer — HALF-LOCAL writer (sample s = mrow0 + ltid)
        if (t + 1 < T && ltid < 64) {
            const int s = mrow0 + ltid;
            const float4 x = sSeq[s * NOBJ + t + 1];
            float4 xr;
            xr.x = __uint_as_float(f2tf32(x.x));
            xr.y = __uint_as_float(f2tf32(x.y));
            xr.z = __uint_as_float(f2tf32(x.z));
            xr.w = __uint_as_float(f2tf32(x.w));
            *reinterpret_cast<float4*>(sAn + s * ASTR + 64) = xr;
        }

        bar_half(barid);   // sync only this half; other half free-runs
    }

    // T == 0: no steps ran, h = 0 everywhere (out is poisoned -> must write)
    if (T == 0) {
        for (int i = tid; i < SPC * 16; i += 512) {
            const int s = i >> 4, q = i & 15;
            const int b = ctaBase + s;
            if (b < B)
                *reinterpret_cast<float4*>(out + (size_t)b * 64 + q * 4) =
                    make_float4(0.f, 0.f, 0.f, 0.f);
        }
    }
}

// ---------------- launch ----------------
extern "C" void kernel_launch(void* const* d_in, const int* in_sizes, int n_in,
                              void* d_out, int out_size) {
    const float* canvas = (const float*)d_in[0];
    const float* W_emb  = (const float*)d_in[1];
    const float* b_emb  = (const float*)d_in[2];
    const float* W_ih   = (const float*)d_in[3];
    const float* W_hh   = (const float*)d_in[4];
    const float* b_ih   = (const float*)d_in[5];
    const float* b_hh   = (const float*)d_in[6];
    float* out = (float*)d_out;

    const int B = in_sizes[0] / ROWF;

    cudaFuncSetAttribute(lstm_kernel, cudaFuncAttributeMaxDynamicSharedMemorySize, SMEM_TOTAL);

    precompute_kernel<<<1, 256>>>(W_emb, b_emb, W_ih, W_hh, b_ih, b_hh);
    count_kernel<<<(B + 7) / 8, 256>>>(canvas, B);
    lstm_kernel<<<(B + SPC - 1) / SPC, 512, SMEM_TOTAL>>>(canvas, out, B);
}

// round 12
// speedup vs baseline: 1.2801x; 1.2801x over previous
#include <cuda_runtime.h>
#include <cuda_fp16.h>
#include <cstdint>

#define NOBJ 25
#define ROWF 100          // floats per canvas row (25*4)
#define SPC  128          // samples per CTA (8 m-tiles)
#define KDIM 80           // padded K: [h(64) | x(4) | 1 | 0-pad(11)] = 5 x k16
#define ASTR 88           // fp16 row stride (176 B -> conflict-free ldmatrix)

// dynamic smem (halves): sB[256*88] | sA0[128*88] | sA1[128*88] | sSeq (float4, 16B aligned)
#define SB_H   (256 * ASTR)              // 22528 halves
#define SA_H   (SPC * ASTR)              // 11264 halves
#define OFF_A0 SB_H
#define OFF_A1 (SB_H + SA_H)
#define OFF_SEQ_BYTES ((SB_H + 2 * SA_H) * 2)            // 90112 B (16B aligned)
#define SMEM_TOTAL (OFF_SEQ_BYTES + SPC * NOBJ * 16)     // 141312 B

__device__ int    g_Tmax;
__device__ __half g_Bmat[256 * KDIM];   // folded weight matrix, gate-permuted rows, fp16

// ---------------- helpers ----------------
__device__ __forceinline__ void mma16(float& d0, float& d1, float& d2, float& d3,
                                      uint32_t a0, uint32_t a1, uint32_t a2, uint32_t a3,
                                      uint32_t b0, uint32_t b1) {
    asm volatile("mma.sync.aligned.m16n8k16.row.col.f32.f16.f16.f32 "
                 "{%0,%1,%2,%3}, {%4,%5,%6,%7}, {%8,%9}, {%0,%1,%2,%3};"
                 : "+f"(d0), "+f"(d1), "+f"(d2), "+f"(d3)
                 : "r"(a0), "r"(a1), "r"(a2), "r"(a3), "r"(b0), "r"(b1));
}

__device__ __forceinline__ void ldm_x4(uint32_t& r0, uint32_t& r1, uint32_t& r2, uint32_t& r3,
                                       uint32_t addr) {
    asm volatile("ldmatrix.sync.aligned.m8n8.x4.shared.b16 {%0,%1,%2,%3}, [%4];"
                 : "=r"(r0), "=r"(r1), "=r"(r2), "=r"(r3) : "r"(addr));
}

__device__ __forceinline__ float tanhapx(float x) {
    float y; asm("tanh.approx.f32 %0, %1;" : "=f"(y) : "f"(x)); return y;
}
__device__ __forceinline__ float sigm_t(float x) {
    return fmaf(tanhapx(0.5f * x), 0.5f, 0.5f);
}

// ---------------- Kernel 0: folded, gate-permuted B matrix [256][80] fp16 ----------------
// n-row mapping: tile=n>>3, pair=(n&7)>>1, which=n&1; u=((tile>>1)<<2)+pair;
// gate = even tile ? (which?f:i) : (which?o:g)   [torch i,f,g,o]
// Row: [0..63]=W_hh[wr][k], [64..67]=(W_ih@W_emb)[wr][d], [68]=total bias, [69..79]=0
__global__ void precompute_kernel(const float* __restrict__ W_emb, const float* __restrict__ b_emb,
                                  const float* __restrict__ W_ih,  const float* __restrict__ W_hh,
                                  const float* __restrict__ b_ih,  const float* __restrict__ b_hh) {
    const int n = threadIdx.x;            // 256 threads, one B-row each
    if (n == 0) g_Tmax = 0;
    const int tile = n >> 3, pair = (n & 7) >> 1, which = n & 1;
    const int u = ((tile >> 1) << 2) + pair;
    const int gate = (tile & 1) ? (2 + which) : which;
    const int wr = gate * 64 + u;

    __half* dst = g_Bmat + n * KDIM;
    for (int k = 0; k < 64; k++)
        dst[k] = __float2half_rn(W_hh[wr * 64 + k]);

    float a0 = 0.f, a1 = 0.f, a2 = 0.f, a3 = 0.f, bias = 0.f;
    for (int k = 0; k < 64; k++) {
        const float wih = W_ih[wr * 64 + k];
        a0 = fmaf(wih, W_emb[k * 4 + 0], a0);
        a1 = fmaf(wih, W_emb[k * 4 + 1], a1);
        a2 = fmaf(wih, W_emb[k * 4 + 2], a2);
        a3 = fmaf(wih, W_emb[k * 4 + 3], a3);
        bias = fmaf(wih, b_emb[k], bias);
    }
    bias += b_ih[wr] + b_hh[wr];
    dst[64] = __float2half_rn(a0);
    dst[65] = __float2half_rn(a1);
    dst[66] = __float2half_rn(a2);
    dst[67] = __float2half_rn(a3);
    dst[68] = __float2half_rn(bias);
    for (int k = 69; k < KDIM; k++) dst[k] = __float2half_rn(0.0f);
}

// ---------------- Kernel 1: batch-wide max valid-object count ----------------
__global__ void count_kernel(const float* __restrict__ canvas, int B) {
    __shared__ int smax;
    if (threadIdx.x == 0) smax = 0;
    __syncthreads();
    const int warp = blockIdx.x * (blockDim.x >> 5) + (threadIdx.x >> 5);
    const int lane = threadIdx.x & 31;
    if (warp < B) {
        int valid = 0;
        if (lane < NOBJ) {
            const float4 v = *reinterpret_cast<const float4*>(canvas + (size_t)warp * ROWF + lane * 4);
            valid = (((v.x + v.y) + v.z) + v.w >= 0.0f) ? 1 : 0;
        }
        const unsigned msk = __ballot_sync(0xFFFFFFFFu, valid);
        if (lane == 0 && msk) atomicMax(&smax, __popc(msk));
    }
    __syncthreads();
    if (threadIdx.x == 0 && smax > 0) atomicMax(&g_Tmax, smax);
}

// ---------------- Kernel 2: fp16 mma.sync LSTM, 128 samples/CTA, 512 threads ----------------
// Warp w: col-group wg=w&7 (gate cols [32wg,32wg+32) = units [8wg,8wg+8)),
//         m-half mh=w>>3 (samples mh*64 .. mh*64+63, 4 m-tiles).
// Thread (gid=lane>>2, tig=lane&3): units u0=8wg+tig, u1=u0+4.
__global__ void __launch_bounds__(512, 1) lstm_kernel(const float* __restrict__ canvas,
                                                      float* __restrict__ out, int B) {
    extern __shared__ __half smh[];
    __half* sB = smh;
    __half* sAbuf[2] = { smh + OFF_A0, smh + OFF_A1 };
    float4* sSeq = reinterpret_cast<float4*>(reinterpret_cast<char*>(smh) + OFF_SEQ_BYTES);

    const int tid  = threadIdx.x;
    const int w    = tid >> 5, lane = tid & 31;
    const int wg   = w & 7, mh = w >> 3;
    const int gid  = lane >> 2, tig = lane & 3;
    const int u0   = wg * 8 + tig, u1 = u0 + 4;
    const int nw   = wg * 32;
    const int ctaBase = blockIdx.x * SPC;

    // ldmatrix lane addressing (b16 elements)
    const int r8 = lane & 7;
    const int a_row = ((lane >> 3) & 1) * 8 + r8;          // row within m-tile
    const int a_col = (lane >> 4) * 8;                     // fp16 col within k16 chunk
    const int b_rowp = ((lane >> 4)) * 8 + r8;             // row within 16-row n-pair
    const int b_col = ((lane >> 3) & 1) * 8;               // fp16 col within k16 chunk
    const uint32_t sBaddr = (uint32_t)__cvta_generic_to_shared(sB);
    const uint32_t sAaddr[2] = { (uint32_t)__cvta_generic_to_shared(sAbuf[0]),
                                 (uint32_t)__cvta_generic_to_shared(sAbuf[1]) };

    // Load B [256][80] -> sB [256][88]
    for (int i = tid; i < 256 * KDIM; i += 512) {
        const int n = i / KDIM, k = i - n * KDIM;
        sB[n * ASTR + k] = g_Bmat[i];
    }
    // Zero A buffers (cols 69..87 stay 0 forever; kc=4 reads 69..79 as zero-pad)
    for (int i = tid; i < 2 * SA_H; i += 512) smh[OFF_A0 + i] = __float2half_rn(0.0f);
    __syncthreads();
    const __half hone = __float2half_rn(1.0f);
    if (tid < SPC) { sAbuf[0][tid * ASTR + 68] = hone; sAbuf[1][tid * ASTR + 68] = hone; }

    // Compaction: 16 warps x 8 samples, stable-compact, pad -1
    #pragma unroll
    for (int m = 0; m < 8; m++) {
        const int s = w * 8 + m;
        const int b = ctaBase + s;
        float4 v = make_float4(-1.f, -1.f, -1.f, -1.f);
        int valid = 0;
        if (b < B && lane < NOBJ) {
            v = *reinterpret_cast<const float4*>(canvas + (size_t)b * ROWF + lane * 4);
            valid = (((v.x + v.y) + v.z) + v.w >= 0.0f) ? 1 : 0;
        }
        const unsigned msk = __ballot_sync(0xFFFFFFFFu, valid);
        const int cnt = __popc(msk);
        if (lane < NOBJ) {
            if (valid) sSeq[s * NOBJ + __popc(msk & ((1u << lane) - 1u))] = v;
            if (lane >= cnt) sSeq[s * NOBJ + lane] = make_float4(-1.f, -1.f, -1.f, -1.f);
        }
    }

    float c_[16];
    #pragma unroll
    for (int i = 0; i < 16; i++) c_[i] = 0.f;

    const int T = g_Tmax;
    __syncthreads();

    // x_0 into buffer 0 (fp16, 8B store)
    if (tid < SPC) {
        const float4 x = sSeq[tid * NOBJ + 0];
        __half2 h01 = __floats2half2_rn(x.x, x.y);
        __half2 h23 = __floats2half2_rn(x.z, x.w);
        uint2 pk = make_uint2(*reinterpret_cast<uint32_t*>(&h01),
                              *reinterpret_cast<uint32_t*>(&h23));
        *reinterpret_cast<uint2*>(sAbuf[0] + tid * ASTR + 64) = pk;
    }
    __syncthreads();

    for (int t = 0; t < T; t++) {
        const uint32_t aBase = sAaddr[t & 1];
        __half* sAn = sAbuf[(t & 1) ^ 1];
        const bool last = (t == T - 1);

        float acc[4][4][4];
        #pragma unroll
        for (int mt = 0; mt < 4; mt++)
            #pragma unroll
            for (int nt = 0; nt < 4; nt++)
                #pragma unroll
                for (int e = 0; e < 4; e++) acc[mt][nt][e] = 0.f;

        #pragma unroll
        for (int kc = 0; kc < 5; kc++) {
            // B: pair p covers n-tiles 2p, 2p+1 -> bfr[p] = {b0(2p), b1(2p), b0(2p+1), b1(2p+1)}
            uint32_t bfr[2][4];
            #pragma unroll
            for (int p = 0; p < 2; p++) {
                const uint32_t addr = sBaddr +
                    (((nw + p * 16 + b_rowp) * ASTR) + kc * 16 + b_col) * 2u;
                ldm_x4(bfr[p][0], bfr[p][1], bfr[p][2], bfr[p][3], addr);
            }
            uint32_t af[4][4];
            #pragma unroll
            for (int mt = 0; mt < 4; mt++) {
                const uint32_t addr = aBase +
                    (((mh * 64 + mt * 16 + a_row) * ASTR) + kc * 16 + a_col) * 2u;
                ldm_x4(af[mt][0], af[mt][1], af[mt][2], af[mt][3], addr);
            }
            #pragma unroll
            for (int mt = 0; mt < 4; mt++)
                #pragma unroll
                for (int nt = 0; nt < 4; nt++)
                    mma16(acc[mt][nt][0], acc[mt][nt][1], acc[mt][nt][2], acc[mt][nt][3],
                          af[mt][0], af[mt][1], af[mt][2], af[mt][3],
                          bfr[nt >> 1][(nt & 1) * 2], bfr[nt >> 1][(nt & 1) * 2 + 1]);
        }

        // Epilogue: 16 (sample,unit) updates; h -> NEXT buffer (fp16); final step -> gmem fp32
        #pragma unroll
        for (int mt = 0; mt < 4; mt++) {
            const int s0 = mh * 64 + mt * 16 + gid;
            #pragma unroll
            for (int q = 0; q < 4; q++) {
                const int ntA = (q >> 1) * 2;
                const int e   = (q & 1) * 2;
                const float iv = acc[mt][ntA][e + 0];
                const float fv = acc[mt][ntA][e + 1];
                const float gv = acc[mt][ntA + 1][e + 0];
                const float ov = acc[mt][ntA + 1][e + 1];
                const int ci = mt * 4 + q;
                const float cn = sigm_t(fv) * c_[ci] + sigm_t(iv) * tanhapx(gv);
                c_[ci] = cn;
                const float hn = sigm_t(ov) * tanhapx(cn);
                const int s = s0 + (q & 1) * 8;
                const int u = (q >> 1) ? u1 : u0;
                sAn[s * ASTR + u] = __float2half_rn(hn);
                if (last) {
                    const int b = ctaBase + s;
                    if (b < B) out[(size_t)b * 64 + u] = hn;
                }
            }
        }

        // x_{t+1} into next buffer (fp16)
        if (t + 1 < T && tid < SPC) {
            const float4 x = sSeq[tid * NOBJ + t + 1];
            __half2 h01 = __floats2half2_rn(x.x, x.y);
            __half2 h23 = __floats2half2_rn(x.z, x.w);
            uint2 pk = make_uint2(*reinterpret_cast<uint32_t*>(&h01),
                                  *reinterpret_cast<uint32_t*>(&h23));
            *reinterpret_cast<uint2*>(sAn + tid * ASTR + 64) = pk;
        }

        __syncthreads();   // single barrier per step
    }

    // T == 0: no steps ran, h = 0 everywhere (out is poisoned -> must write)
    if (T == 0) {
        for (int i = tid; i < SPC * 16; i += 512) {
            const int s = i >> 4, q = i & 15;
            const int b = ctaBase + s;
            if (b < B)
                *reinterpret_cast<float4*>(out + (size_t)b * 64 + q * 4) =
                    make_float4(0.f, 0.f, 0.f, 0.f);
        }
    }
}

// ---------------- launch ----------------
extern "C" void kernel_launch(void* const* d_in, const int* in_sizes, int n_in,
                              void* d_out, int out_size) {
    const float* canvas = (const float*)d_in[0];
    const float* W_emb  = (const float*)d_in[1];
    const float* b_emb  = (const float*)d_in[2];
    const float* W_ih   = (const float*)d_in[3];
    const float* W_hh   = (const float*)d_in[4];
    const float* b_ih   = (const float*)d_in[5];
    const float* b_hh   = (const float*)d_in[6];
    float* out = (float*)d_out;

    const int B = in_sizes[0] / ROWF;

    cudaFuncSetAttribute(lstm_kernel, cudaFuncAttributeMaxDynamicSharedMemorySize, SMEM_TOTAL);

    precompute_kernel<<<1, 256>>>(W_emb, b_emb, W_ih, W_hh, b_ih, b_hh);
    count_kernel<<<(B + 7) / 8, 256>>>(canvas, B);
    lstm_kernel<<<(B + SPC - 1) / SPC, 512, SMEM_TOTAL>>>(canvas, out, B);
}

// round 13
// speedup vs baseline: 1.6769x; 1.3100x over previous
#include <cuda_runtime.h>
#include <cuda_fp16.h>
#include <cstdint>

#define NOBJ 25
#define ROWF 100          // floats per canvas row (25*4)
#define SPC  128          // samples per CTA (8 m-tiles)
#define KDIM 80           // padded K: [h(64) | x(4) | 1 | 0-pad(11)] = 5 x k16
#define ASTR 88           // fp16 row stride (176 B -> conflict-free ldmatrix)

// dynamic smem (halves): sB[256*88] | sA0[128*88] | sA1[128*88] | sSeq (float4, 16B aligned)
#define SB_H   (256 * ASTR)              // 22528 halves
#define SA_H   (SPC * ASTR)              // 11264 halves
#define OFF_A0 SB_H
#define OFF_A1 (SB_H + SA_H)
#define OFF_SEQ_BYTES ((SB_H + 2 * SA_H) * 2)            // 90112 B (16B aligned)
#define SMEM_TOTAL (OFF_SEQ_BYTES + SPC * NOBJ * 16)     // 141312 B

__device__ int    g_Tmax;
__device__ __half g_Bmat[256 * KDIM];   // folded weight matrix, gate-permuted rows, fp16

// ---------------- helpers ----------------
__device__ __forceinline__ void mma16(float& d0, float& d1, float& d2, float& d3,
                                      uint32_t a0, uint32_t a1, uint32_t a2, uint32_t a3,
                                      uint32_t b0, uint32_t b1) {
    asm volatile("mma.sync.aligned.m16n8k16.row.col.f32.f16.f16.f32 "
                 "{%0,%1,%2,%3}, {%4,%5,%6,%7}, {%8,%9}, {%0,%1,%2,%3};"
                 : "+f"(d0), "+f"(d1), "+f"(d2), "+f"(d3)
                 : "r"(a0), "r"(a1), "r"(a2), "r"(a3), "r"(b0), "r"(b1));
}

__device__ __forceinline__ void ldm_x4(uint32_t& r0, uint32_t& r1, uint32_t& r2, uint32_t& r3,
                                       uint32_t addr) {
    asm volatile("ldmatrix.sync.aligned.m8n8.x4.shared.b16 {%0,%1,%2,%3}, [%4];"
                 : "=r"(r0), "=r"(r1), "=r"(r2), "=r"(r3) : "r"(addr));
}

__device__ __forceinline__ float tanhapx(float x) {
    float y; asm("tanh.approx.f32 %0, %1;" : "=f"(y) : "f"(x)); return y;
}
__device__ __forceinline__ float sigm_t(float x) {
    return fmaf(tanhapx(0.5f * x), 0.5f, 0.5f);
}

// ---------------- Kernel 0: folded, gate-permuted B matrix [256][80] fp16 ----------------
// n-row mapping: tile=n>>3, pair=(n&7)>>1, which=n&1; u=((tile>>1)<<2)+pair;
// gate = even tile ? (which?f:i) : (which?o:g)   [torch i,f,g,o]
// Row: [0..63]=W_hh[wr][k], [64..67]=(W_ih@W_emb)[wr][d], [68]=total bias, [69..79]=0
__global__ void precompute_kernel(const float* __restrict__ W_emb, const float* __restrict__ b_emb,
                                  const float* __restrict__ W_ih,  const float* __restrict__ W_hh,
                                  const float* __restrict__ b_ih,  const float* __restrict__ b_hh) {
    const int n = threadIdx.x;            // 256 threads, one B-row each
    if (n == 0) g_Tmax = 0;
    const int tile = n >> 3, pair = (n & 7) >> 1, which = n & 1;
    const int u = ((tile >> 1) << 2) + pair;
    const int gate = (tile & 1) ? (2 + which) : which;
    const int wr = gate * 64 + u;

    __half* dst = g_Bmat + n * KDIM;
    for (int k = 0; k < 64; k++)
        dst[k] = __float2half_rn(W_hh[wr * 64 + k]);

    float a0 = 0.f, a1 = 0.f, a2 = 0.f, a3 = 0.f, bias = 0.f;
    for (int k = 0; k < 64; k++) {
        const float wih = W_ih[wr * 64 + k];
        a0 = fmaf(wih, W_emb[k * 4 + 0], a0);
        a1 = fmaf(wih, W_emb[k * 4 + 1], a1);
        a2 = fmaf(wih, W_emb[k * 4 + 2], a2);
        a3 = fmaf(wih, W_emb[k * 4 + 3], a3);
        bias = fmaf(wih, b_emb[k], bias);
    }
    bias += b_ih[wr] + b_hh[wr];
    dst[64] = __float2half_rn(a0);
    dst[65] = __float2half_rn(a1);
    dst[66] = __float2half_rn(a2);
    dst[67] = __float2half_rn(a3);
    dst[68] = __float2half_rn(bias);
    for (int k = 69; k < KDIM; k++) dst[k] = __float2half_rn(0.0f);
}

// ---------------- Kernel 1: batch-wide max valid-object count ----------------
__global__ void count_kernel(const float* __restrict__ canvas, int B) {
    __shared__ int smax;
    if (threadIdx.x == 0) smax = 0;
    __syncthreads();
    const int warp = blockIdx.x * (blockDim.x >> 5) + (threadIdx.x >> 5);
    const int lane = threadIdx.x & 31;
    if (warp < B) {
        int valid = 0;
        if (lane < NOBJ) {
            const float4 v = *reinterpret_cast<const float4*>(canvas + (size_t)warp * ROWF + lane * 4);
            valid = (((v.x + v.y) + v.z) + v.w >= 0.0f) ? 1 : 0;
        }
        const unsigned msk = __ballot_sync(0xFFFFFFFFu, valid);
        if (lane == 0 && msk) atomicMax(&smax, __popc(msk));
    }
    __syncthreads();
    if (threadIdx.x == 0 && smax > 0) atomicMax(&g_Tmax, smax);
}

// ---------------- Kernel 2: fp16 mma.sync LSTM, 128 samples/CTA, 512 threads ----------------
// Warp w: col-group wg=w&7 (gate cols [32wg,32wg+32) = units [8wg,8wg+8)),
//         m-half mh=w>>3 (samples mh*64 .. mh*64+63, 4 m-tiles).
// Thread (gid=lane>>2, tig=lane&3): units u0=8wg+tig, u1=u0+4.
// B fragments persistent in registers (step-invariant); mt-outer loop so each
// m-tile's MUFU epilogue overlaps the next m-tile's HMMAs.
__global__ void __launch_bounds__(512, 1) lstm_kernel(const float* __restrict__ canvas,
                                                      float* __restrict__ out, int B) {
    extern __shared__ __half smh[];
    __half* sB = smh;
    __half* sAbuf[2] = { smh + OFF_A0, smh + OFF_A1 };
    float4* sSeq = reinterpret_cast<float4*>(reinterpret_cast<char*>(smh) + OFF_SEQ_BYTES);

    const int tid  = threadIdx.x;
    const int w    = tid >> 5, lane = tid & 31;
    const int wg   = w & 7, mh = w >> 3;
    const int gid  = lane >> 2, tig = lane & 3;
    const int u0   = wg * 8 + tig, u1 = u0 + 4;
    const int nw   = wg * 32;
    const int ctaBase = blockIdx.x * SPC;

    // ldmatrix lane addressing (b16 elements)
    const int r8 = lane & 7;
    const int a_row = ((lane >> 3) & 1) * 8 + r8;          // row within m-tile
    const int a_col = (lane >> 4) * 8;                     // fp16 col within k16 chunk
    const int b_rowp = ((lane >> 4)) * 8 + r8;             // row within 16-row n-pair
    const int b_col = ((lane >> 3) & 1) * 8;               // fp16 col within k16 chunk
    const uint32_t sBaddr = (uint32_t)__cvta_generic_to_shared(sB);
    const uint32_t sAaddr[2] = { (uint32_t)__cvta_generic_to_shared(sAbuf[0]),
                                 (uint32_t)__cvta_generic_to_shared(sAbuf[1]) };

    // Load B [256][80] -> sB [256][88]
    for (int i = tid; i < 256 * KDIM; i += 512) {
        const int n = i / KDIM, k = i - n * KDIM;
        sB[n * ASTR + k] = g_Bmat[i];
    }
    // Zero A buffers (cols 69..87 stay 0 forever; kc=4 reads 69..79 as zero-pad)
    for (int i = tid; i < 2 * SA_H; i += 512) smh[OFF_A0 + i] = __float2half_rn(0.0f);
    __syncthreads();
    const __half hone = __float2half_rn(1.0f);
    if (tid < SPC) { sAbuf[0][tid * ASTR + 68] = hone; sAbuf[1][tid * ASTR + 68] = hone; }

    // Compaction: 16 warps x 8 samples, stable-compact, pad -1
    #pragma unroll
    for (int m = 0; m < 8; m++) {
        const int s = w * 8 + m;
        const int b = ctaBase + s;
        float4 v = make_float4(-1.f, -1.f, -1.f, -1.f);
        int valid = 0;
        if (b < B && lane < NOBJ) {
            v = *reinterpret_cast<const float4*>(canvas + (size_t)b * ROWF + lane * 4);
            valid = (((v.x + v.y) + v.z) + v.w >= 0.0f) ? 1 : 0;
        }
        const unsigned msk = __ballot_sync(0xFFFFFFFFu, valid);
        const int cnt = __popc(msk);
        if (lane < NOBJ) {
            if (valid) sSeq[s * NOBJ + __popc(msk & ((1u << lane) - 1u))] = v;
            if (lane >= cnt) sSeq[s * NOBJ + lane] = make_float4(-1.f, -1.f, -1.f, -1.f);
        }
    }
    __syncthreads();   // sB fully written before fragment preload

    // B fragments: persistent registers for the whole kernel (5 kc x 2 pairs x 4 = 40 regs)
    uint32_t bfr[5][2][4];
    #pragma unroll
    for (int kc = 0; kc < 5; kc++)
        #pragma unroll
        for (int p = 0; p < 2; p++) {
            const uint32_t addr = sBaddr +
                (((nw + p * 16 + b_rowp) * ASTR) + kc * 16 + b_col) * 2u;
            ldm_x4(bfr[kc][p][0], bfr[kc][p][1], bfr[kc][p][2], bfr[kc][p][3], addr);
        }

    float c_[16];
    #pragma unroll
    for (int i = 0; i < 16; i++) c_[i] = 0.f;

    const int T = g_Tmax;

    // x_0 into buffer 0 (fp16, 8B store)
    if (tid < SPC) {
        const float4 x = sSeq[tid * NOBJ + 0];
        __half2 h01 = __floats2half2_rn(x.x, x.y);
        __half2 h23 = __floats2half2_rn(x.z, x.w);
        uint2 pk = make_uint2(*reinterpret_cast<uint32_t*>(&h01),
                              *reinterpret_cast<uint32_t*>(&h23));
        *reinterpret_cast<uint2*>(sAbuf[0] + tid * ASTR + 64) = pk;
    }
    __syncthreads();

    for (int t = 0; t < T; t++) {
        const uint32_t aBase = sAaddr[t & 1];
        __half* sAn = sAbuf[(t & 1) ^ 1];
        const bool last = (t == T - 1);

        // mt-outer: accumulate one m-tile (16 live acc regs), then its epilogue
        // issues MUFU while the next m-tile's HMMAs occupy the tensor pipe.
        #pragma unroll
        for (int mt = 0; mt < 4; mt++) {
            float acc[4][4];
            #pragma unroll
            for (int nt = 0; nt < 4; nt++)
                #pragma unroll
                for (int e = 0; e < 4; e++) acc[nt][e] = 0.f;

            #pragma unroll
            for (int kc = 0; kc < 5; kc++) {
                uint32_t a0, a1, a2, a3;
                const uint32_t addr = aBase +
                    (((mh * 64 + mt * 16 + a_row) * ASTR) + kc * 16 + a_col) * 2u;
                ldm_x4(a0, a1, a2, a3, addr);
                #pragma unroll
                for (int nt = 0; nt < 4; nt++)
                    mma16(acc[nt][0], acc[nt][1], acc[nt][2], acc[nt][3],
                          a0, a1, a2, a3,
                          bfr[kc][nt >> 1][(nt & 1) * 2], bfr[kc][nt >> 1][(nt & 1) * 2 + 1]);
            }

            const int s0 = mh * 64 + mt * 16 + gid;
            #pragma unroll
            for (int q = 0; q < 4; q++) {
                const int ntA = (q >> 1) * 2;
                const int e   = (q & 1) * 2;
                const float iv = acc[ntA][e + 0];
                const float fv = acc[ntA][e + 1];
                const float gv = acc[ntA + 1][e + 0];
                const float ov = acc[ntA + 1][e + 1];
                const int ci = mt * 4 + q;
                const float cn = sigm_t(fv) * c_[ci] + sigm_t(iv) * tanhapx(gv);
                c_[ci] = cn;
                const float hn = sigm_t(ov) * tanhapx(cn);
                const int s = s0 + (q & 1) * 8;
                const int u = (q >> 1) ? u1 : u0;
                sAn[s * ASTR + u] = __float2half_rn(hn);
                if (last) {
                    const int b = ctaBase + s;
                    if (b < B) out[(size_t)b * 64 + u] = hn;
                }
            }
        }

        // x_{t+1} into next buffer (fp16)
        if (t + 1 < T && tid < SPC) {
            const float4 x = sSeq[tid * NOBJ + t + 1];
            __half2 h01 = __floats2half2_rn(x.x, x.y);
            __half2 h23 = __floats2half2_rn(x.z, x.w);
            uint2 pk = make_uint2(*reinterpret_cast<uint32_t*>(&h01),
                                  *reinterpret_cast<uint32_t*>(&h23));
            *reinterpret_cast<uint2*>(sAn + tid * ASTR + 64) = pk;
        }

        __syncthreads();   // single barrier per step
    }

    // T == 0: no steps ran, h = 0 everywhere (out is poisoned -> must write)
    if (T == 0) {
        for (int i = tid; i < SPC * 16; i += 512) {
            const int s = i >> 4, q = i & 15;
            const int b = ctaBase + s;
            if (b < B)
                *reinterpret_cast<float4*>(out + (size_t)b * 64 + q * 4) =
                    make_float4(0.f, 0.f, 0.f, 0.f);
        }
    }
}

// ---------------- launch ----------------
extern "C" void kernel_launch(void* const* d_in, const int* in_sizes, int n_in,
                              void* d_out, int out_size) {
    const float* canvas = (const float*)d_in[0];
    const float* W_emb  = (const float*)d_in[1];
    const float* b_emb  = (const float*)d_in[2];
    const float* W_ih   = (const float*)d_in[3];
    const float* W_hh   = (const float*)d_in[4];
    const float* b_ih   = (const float*)d_in[5];
    const float* b_hh   = (const float*)d_in[6];
    float* out = (float*)d_out;

    const int B = in_sizes[0] / ROWF;

    cudaFuncSetAttribute(lstm_kernel, cudaFuncAttributeMaxDynamicSharedMemorySize, SMEM_TOTAL);

    precompute_kernel<<<1, 256>>>(W_emb, b_emb, W_ih, W_hh, b_ih, b_hh);
    count_kernel<<<(B + 7) / 8, 256>>>(canvas, B);
    lstm_kernel<<<(B + SPC - 1) / SPC, 512, SMEM_TOTAL>>>(canvas, out, B);
}